// round 14
// baseline (speedup 1.0000x reference)
#include <cuda_runtime.h>
#include <cuda_fp16.h>
#include <math.h>
#include <stdint.h>

#define N_ROWS 32768
#define D_IN   768
#define D_H1   2048
#define D_H2   1024
#define D_E    64
#define N_CODE 256
#define N_PAIR 4096
#define N_TRIP 8192

#define VQ_OFF    25165824
#define IDX_OFF   25165825
#define XQ_OFF    25198593
#define OUTER_OFF 27295745
#define TRIP_OFF  27295746
#define QD_OFF    27295747

#define FLAG_EPS 2e-5f

// ---------------- scratch (device globals) ----------------
#define W0_OFF 0
#define W1_OFF 1572864
#define W2_OFF 3670016
#define W3_OFF 3735552
#define W4_OFF 3801088
#define W5_OFF 5898240
#define W_TOT  7471104
__device__ __align__(16) __half g_wh[W_TOT];
__device__ __align__(16) __half g_wl[W_TOT];

#define ACT_ELEMS ((size_t)N_ROWS * 2048)
__device__ __align__(16) __half g_a0h[ACT_ELEMS];
__device__ __align__(16) __half g_a0l[ACT_ELEMS];
__device__ __align__(16) __half g_a1h[ACT_ELEMS];   // also: zh after enc L2
__device__ __align__(16) __half g_a1l[ACT_ELEMS];   // also: zl after enc L2

// decoder-on-codebook buffers (M=256)
__device__ __align__(16) __half g_cbh[N_CODE * D_E];
__device__ __align__(16) __half g_cbl[N_CODE * D_E];
__device__ __align__(16) __half g_dh1[N_CODE * D_H2];
__device__ __align__(16) __half g_dl1[N_CODE * D_H2];
__device__ __align__(16) __half g_dh2[N_CODE * D_H1];
__device__ __align__(16) __half g_dl2[N_CODE * D_H1];
__device__ float g_dec3[N_CODE * D_IN];

__device__ float g_z [(size_t)N_ROWS * D_E];
__device__ float g_qz[(size_t)N_ROWS * D_E];
__device__ float g_zg[(size_t)N_ROWS * D_E];
__device__ float g_rep1[(size_t)N_ROWS * D_H1];   // also dots[32768,256]
__device__ float g_rep2[(size_t)N_ROWS * D_H2];   // also split-K partials
__device__ float g_cbn[N_CODE * D_E];
__device__ float g_G  [N_CODE * N_CODE];
__device__ float g_lse[N_CODE];
__device__ float g_zero[2048];
__device__ int   g_idx[N_ROWS];
__device__ int   g_cnt[N_CODE];
__device__ int   g_rowlist[N_ROWS];
__device__ int   g_nflag;
__device__ double g_acc[4];

// ---------------- helpers ----------------
__device__ __forceinline__ uint32_t smem_u32(const void* p) {
    uint32_t a;
    asm("{ .reg .u64 t; cvta.to.shared.u64 t, %1; cvt.u32.u64 %0, t; }" : "=r"(a) : "l"(p));
    return a;
}
#define LDSM4(r, a) \
    asm volatile("ldmatrix.sync.aligned.m8n8.x4.shared.b16 {%0,%1,%2,%3}, [%4];" \
        : "=r"((r)[0]), "=r"((r)[1]), "=r"((r)[2]), "=r"((r)[3]) : "r"(a))
#define MMA16816(d, a, b) \
    asm volatile("mma.sync.aligned.m16n8k16.row.col.f32.f16.f16.f32 " \
        "{%0,%1,%2,%3}, {%4,%5,%6,%7}, {%8,%9}, {%0,%1,%2,%3};" \
        : "+f"((d)[0]), "+f"((d)[1]), "+f"((d)[2]), "+f"((d)[3]) \
        : "r"((a)[0]), "r"((a)[1]), "r"((a)[2]), "r"((a)[3]), "r"((b)[0]), "r"((b)[1]))
#define CP_ASYNC16(sa, ga) \
    asm volatile("cp.async.cg.shared.global [%0], [%1], 16;" :: "r"(sa), "l"(ga))
#define CP_COMMIT() asm volatile("cp.async.commit_group;" ::: "memory")

// ---------------- prep kernels ----------------
__global__ void split_kernel(const float* __restrict__ src,
                             __half* __restrict__ hi,
                             __half* __restrict__ lo, size_t n) {
    for (size_t i = (size_t)blockIdx.x * blockDim.x + threadIdx.x; i < n;
         i += (size_t)gridDim.x * blockDim.x) {
        float v = src[i];
        __half h = __float2half(v);
        hi[i] = h;
        if (lo) lo[i] = __float2half(v - __half2float(h));
    }
}

// all-6-weights transpose + split, one launch (block-range partition)
struct W6 {
    const float* W[6];
    __half* hi[6];
    __half* lo[6];
    int K[6], N[6], base[6], nbx[6];
};

__global__ __launch_bounds__(256)
void wprep_all(W6 d) {
    __shared__ float t[32][33];
    int b = blockIdx.x;
    int w = 0;
#pragma unroll
    for (int i = 1; i < 6; i++) if (b >= d.base[i]) w = i;
    int bx = b - d.base[w];
    int nbx = d.nbx[w];
    int K = d.K[w], N = d.N[w];
    int nb = (bx % nbx) * 32;
    int kb = (bx / nbx) * 32;
    const float* W = d.W[w];
    __half* hi = d.hi[w];
    __half* lo = d.lo[w];

    int tx = threadIdx.x & 31, ty = threadIdx.x >> 5;
#pragma unroll
    for (int j = 0; j < 32; j += 8)
        t[ty + j][tx] = W[(size_t)(kb + ty + j) * N + nb + tx];
    __syncthreads();
#pragma unroll
    for (int j = 0; j < 32; j += 8) {
        float v = t[tx][ty + j];
        size_t o = (size_t)(nb + ty + j) * K + kb + tx;
        __half h = __float2half(v);
        hi[o] = h;
        lo[o] = __float2half(v - __half2float(h));
    }
}

// ---------------- fp16 multi-term mma GEMM (BN=64, 2 CTAs/SM) ----------------
// TERMS=3: AhBh+AlBh+AhBl; TERMS=1: AhBh.
// OMODE 0: fp32 out; 1: fp16 hi/lo; 2: fp16 hi only; 3: fp32 + hi/lo.
// AF32: A fp32 in gmem, fused hi/lo split (B: 4-ring/3-deep; A: 3-ring, 1 sync/iter).
// Split-K (std path only): gridDim.z slices of Kslice each.
template<int BN, bool RELU, int OMODE, int TERMS, bool AF32>
__global__ __launch_bounds__(256, 2)
void gemm_mma(const float* __restrict__ Af,
              const __half* __restrict__ Ahi, const __half* __restrict__ Alo,
              const __half* __restrict__ Bhi, const __half* __restrict__ Blo,
              const float* __restrict__ bias,
              float* __restrict__ Of,
              __half* __restrict__ Ohi, __half* __restrict__ Olo,
              int Nn, int K, int Kslice, size_t pstride)
{
    constexpr int WARPS_N = 2;
    constexpr int WM = 32;
    constexpr int WN = BN / WARPS_N;   // 32
    constexpr int MT = 2;
    constexpr int NT = WN / 8;         // 4
    constexpr int PITCH = 80;
    constexpr int BROWS = (TERMS == 3) ? 2 * BN : BN;
    constexpr int AROWS = (TERMS == 3) ? 256 : 128;
    constexpr int BSTAGE = BROWS * PITCH;
    constexpr int ASTAGE = AROWS * PITCH;
    constexpr int STAGE = (256 + 2 * BN) * PITCH;   // std stage stride
    constexpr int LROWS = (TERMS == 3) ? (256 + 2 * BN) : (128 + BN);

    extern __shared__ __align__(16) char sm[];
    const int tid  = threadIdx.x;
    const int lane = tid & 31, wid = tid >> 5;
    const int wm = wid / WARPS_N, wn = wid % WARPS_N;
    const int row0 = blockIdx.y * 128;
    const int col0 = blockIdx.x * BN;
    const int kstart = blockIdx.z * Kslice;
    const uint32_t sb = smem_u32(sm);
    const uint32_t sbA_af = sb + 4 * BSTAGE;   // AF32: A region after FOUR B stages

    const uint32_t aoff = ((lane & 7) + ((lane >> 3) & 1) * 8) * PITCH + ((lane >> 4) << 4);
    const uint32_t boff = ((lane & 7) + ((lane >> 4) & 1) * 8) * PITCH + (((lane >> 3) & 1) << 4);

    const int nk = Kslice >> 5;

    float acc[MT][NT][4];
#pragma unroll
    for (int mi = 0; mi < MT; mi++)
#pragma unroll
        for (int ni = 0; ni < NT; ni++)
#pragma unroll
            for (int q = 0; q < 4; q++) acc[mi][ni][q] = 0.f;

    auto do_mma = [&](uint32_t sA, uint32_t sB) {
#pragma unroll
        for (int ks = 0; ks < 2; ks++) {
            uint32_t kofs = ks * 32;
            uint32_t ah[MT][4], al[MT][4], bh[NT][2], bl[NT][2];
#pragma unroll
            for (int mi = 0; mi < MT; mi++) {
                uint32_t base = sA + (uint32_t)(wm * WM + mi * 16) * PITCH + aoff + kofs;
                LDSM4(ah[mi], base);
                if (TERMS == 3) LDSM4(al[mi], base + 128 * PITCH);
            }
#pragma unroll
            for (int np = 0; np < NT / 2; np++) {
                uint32_t base = sB + (uint32_t)(wn * WN + np * 16) * PITCH + boff + kofs;
                uint32_t r[4];
                LDSM4(r, base);
                bh[2 * np][0] = r[0]; bh[2 * np][1] = r[1];
                bh[2 * np + 1][0] = r[2]; bh[2 * np + 1][1] = r[3];
                if (TERMS == 3) {
                    LDSM4(r, base + BN * PITCH);
                    bl[2 * np][0] = r[0]; bl[2 * np][1] = r[1];
                    bl[2 * np + 1][0] = r[2]; bl[2 * np + 1][1] = r[3];
                }
            }
#pragma unroll
            for (int mi = 0; mi < MT; mi++)
#pragma unroll
                for (int ni = 0; ni < NT; ni++) MMA16816(acc[mi][ni], ah[mi], bh[ni]);
            if (TERMS == 3) {
#pragma unroll
                for (int mi = 0; mi < MT; mi++)
#pragma unroll
                    for (int ni = 0; ni < NT; ni++) MMA16816(acc[mi][ni], al[mi], bh[ni]);
#pragma unroll
                for (int mi = 0; mi < MT; mi++)
#pragma unroll
                    for (int ni = 0; ni < NT; ni++) MMA16816(acc[mi][ni], ah[mi], bl[ni]);
            }
        }
    };

    if constexpr (!AF32) {
        auto load_stage = [&](int i) {
            uint32_t sbase = sb + (i % 3) * STAGE;
            int k0 = kstart + (i << 5);
#pragma unroll
            for (int c = tid; c < LROWS * 4; c += 256) {
                int r = c >> 2, ch = c & 3;
                const __half* g;
                int srow = r;
                if (TERMS == 1) {
                    if (r < 128) g = Ahi + (size_t)(row0 + r) * K;
                    else { g = Bhi + (size_t)(col0 + r - 128) * K; srow = r + 128; }
                } else {
                    if (r < 128)            g = Ahi + (size_t)(row0 + r) * K;
                    else if (r < 256)       g = Alo + (size_t)(row0 + r - 128) * K;
                    else if (r < 256 + BN)  g = Bhi + (size_t)(col0 + r - 256) * K;
                    else                    g = Blo + (size_t)(col0 + r - 256 - BN) * K;
                }
                CP_ASYNC16(sbase + srow * PITCH + ch * 16, g + k0 + ch * 8);
            }
            CP_COMMIT();
        };
        load_stage(0);
        if (1 < nk) load_stage(1);
        for (int i = 0; i < nk; i++) {
            if (i + 1 < nk) asm volatile("cp.async.wait_group 1;" ::: "memory");
            else            asm volatile("cp.async.wait_group 0;" ::: "memory");
            __syncthreads();
            if (i + 2 < nk) load_stage(i + 2);
            uint32_t sA = sb + (i % 3) * STAGE;
            do_mma(sA, sA + 256 * PITCH);
        }
    } else {
        // B: 4-stage ring, 3-deep prefetch. A: LDG fp32 + fused split, 3-ring.
        auto load_B = [&](int i) {
            uint32_t sbase = sb + (i & 3) * BSTAGE;
            int k0 = i << 5;
#pragma unroll
            for (int c = tid; c < BROWS * 4; c += 256) {
                int r = c >> 2, ch = c & 3;
                const __half* g;
                if (TERMS == 3 && r >= BN) g = Blo + (size_t)(col0 + r - BN) * K;
                else                       g = Bhi + (size_t)(col0 + r) * K;
                CP_ASYNC16(sbase + r * PITCH + ch * 16, g + k0 + ch * 8);
            }
            CP_COMMIT();
        };
        float4 Ar[4], An[4];
        auto ldgA = [&](int i, float4* R) {
            int k0 = i << 5;
#pragma unroll
            for (int it = 0; it < 4; it++) {
                int f4 = tid + 256 * it;
                int r = f4 >> 3, c4 = f4 & 7;
                R[it] = *reinterpret_cast<const float4*>(
                    Af + (size_t)(row0 + r) * K + k0 + c4 * 4);
            }
        };
        auto cvtsts = [&](int i, const float4* R) {
            uint32_t abase = sbA_af + (i % 3) * ASTAGE;
#pragma unroll
            for (int it = 0; it < 4; it++) {
                int f4 = tid + 256 * it;
                int r = f4 >> 3, c4 = f4 & 7;
                uint32_t off = abase + (uint32_t)r * PITCH + c4 * 8;
                __half2 h01 = __floats2half2_rn(R[it].x, R[it].y);
                __half2 h23 = __floats2half2_rn(R[it].z, R[it].w);
                asm volatile("st.shared.v2.b32 [%0], {%1,%2};"
                    :: "r"(off), "r"(*(const uint32_t*)&h01), "r"(*(const uint32_t*)&h23));
                if (TERMS == 3) {
                    __half2 l01 = __floats2half2_rn(R[it].x - __half2float(__low2half(h01)),
                                                    R[it].y - __half2float(__high2half(h01)));
                    __half2 l23 = __floats2half2_rn(R[it].z - __half2float(__low2half(h23)),
                                                    R[it].w - __half2float(__high2half(h23)));
                    asm volatile("st.shared.v2.b32 [%0], {%1,%2};"
                        :: "r"(off + 128 * PITCH),
                           "r"(*(const uint32_t*)&l01), "r"(*(const uint32_t*)&l23));
                }
            }
        };
        ldgA(0, Ar);
        load_B(0);
        if (1 < nk) load_B(1);
        if (2 < nk) load_B(2);
        for (int i = 0; i < nk; i++) {
            if (i + 1 < nk) ldgA(i + 1, An);
            cvtsts(i, Ar);   // writes A-buf i%3; conflicting reader was do_mma(i-3) < sync(i-2)
            int rem = nk - 1 - i;
            if (rem >= 2)      asm volatile("cp.async.wait_group 2;" ::: "memory");
            else if (rem == 1) asm volatile("cp.async.wait_group 1;" ::: "memory");
            else               asm volatile("cp.async.wait_group 0;" ::: "memory");
            __syncthreads();
            if (i + 3 < nk) load_B(i + 3);   // writes (i+3)&3 != i&3
            do_mma(sbA_af + (i % 3) * ASTAGE, sb + (i & 3) * BSTAGE);
#pragma unroll
            for (int it = 0; it < 4; it++) Ar[it] = An[it];
        }
    }

#pragma unroll
    for (int mi = 0; mi < MT; mi++) {
        int rbase = row0 + wm * WM + mi * 16 + (lane >> 2);
#pragma unroll
        for (int ni = 0; ni < NT; ni++) {
            int c = col0 + wn * WN + ni * 8 + (lane & 3) * 2;
            float b0 = __ldg(&bias[c]), b1 = __ldg(&bias[c + 1]);
#pragma unroll
            for (int h = 0; h < 2; h++) {
                float v0 = acc[mi][ni][2 * h]     + b0;
                float v1 = acc[mi][ni][2 * h + 1] + b1;
                if (RELU) { v0 = fmaxf(v0, 0.f); v1 = fmaxf(v1, 0.f); }
                size_t o = (size_t)(rbase + 8 * h) * Nn + c + blockIdx.z * pstride;
                if (OMODE == 0 || OMODE == 3)
                    *reinterpret_cast<float2*>(Of + o) = make_float2(v0, v1);
                if (OMODE == 1 || OMODE == 2 || OMODE == 3) {
                    __half2 hh;
                    hh.x = __float2half(v0);
                    hh.y = __float2half(v1);
                    *reinterpret_cast<__half2*>(Ohi + o) = hh;
                    if (OMODE == 1 || OMODE == 3) {
                        __half2 ll;
                        ll.x = __float2half(v0 - __half2float(hh.x));
                        ll.y = __float2half(v1 - __half2float(hh.y));
                        *reinterpret_cast<__half2*>(Olo + o) = ll;
                    }
                }
            }
        }
    }
}

#define SMEM_STD      (3 * (256 + 128) * 80)                   // 92160
#define SMEM_AF32_T3  (4 * 128 * 80 + 3 * 256 * 80)            // 102400
#define SMEM_AF32_T1  (4 * 64 * 80 + 3 * 128 * 80)             // 51200

// ---------------- split-K reduce: C = act(sum_z P[z] + bias) ----------------
template<bool RELU, int OMODE>
__global__ __launch_bounds__(256)
void reduce_split(const float* __restrict__ P, int S, size_t slice, int Nn,
                  const float* __restrict__ bias,
                  float* __restrict__ Of, __half* __restrict__ Ohi, __half* __restrict__ Olo,
                  size_t total4)
{
    for (size_t i = (size_t)blockIdx.x * blockDim.x + threadIdx.x; i < total4;
         i += (size_t)gridDim.x * blockDim.x) {
        size_t e0 = i * 4;
        float4 s = *reinterpret_cast<const float4*>(P + e0);
        for (int z = 1; z < S; z++) {
            float4 v = *reinterpret_cast<const float4*>(P + z * slice + e0);
            s.x += v.x; s.y += v.y; s.z += v.z; s.w += v.w;
        }
        int c = (int)(e0 % Nn);
        s.x += bias[c]; s.y += bias[c + 1]; s.z += bias[c + 2]; s.w += bias[c + 3];
        if (RELU) {
            s.x = fmaxf(s.x, 0.f); s.y = fmaxf(s.y, 0.f);
            s.z = fmaxf(s.z, 0.f); s.w = fmaxf(s.w, 0.f);
        }
        if (OMODE == 0) {
            *reinterpret_cast<float4*>(Of + e0) = s;
        } else {
            __half2 h01 = __floats2half2_rn(s.x, s.y);
            __half2 h23 = __floats2half2_rn(s.z, s.w);
            __half2 l01 = __floats2half2_rn(s.x - __half2float(__low2half(h01)),
                                            s.y - __half2float(__high2half(h01)));
            __half2 l23 = __floats2half2_rn(s.z - __half2float(__low2half(h23)),
                                            s.w - __half2float(__high2half(h23)));
            *reinterpret_cast<__half2*>(Ohi + e0)     = h01;
            *reinterpret_cast<__half2*>(Ohi + e0 + 2) = h23;
            *reinterpret_cast<__half2*>(Olo + e0)     = l01;
            *reinterpret_cast<__half2*>(Olo + e0 + 2) = l23;
        }
    }
}

// ---------------- fp32 small-M GEMM (repair path; grid-strided rows) --------
template<bool RELU>
__global__ __launch_bounds__(256)
void sgemm32(const float* __restrict__ A, const float* __restrict__ B,
             const float* __restrict__ bias, float* __restrict__ C,
             const int* __restrict__ rowmap, const int* __restrict__ nf_ptr,
             int N, int K)
{
    const int nf = *nf_ptr;
    __shared__ float As[32][33];
    __shared__ float Bs[32][64];
    const int tid = threadIdx.x;
    const int ty = tid >> 4;
    const int tx = tid & 15;
    const int col0 = blockIdx.x * 64;

    // grid-strided over 32-row chunks: correct for ANY nf, no dead-block army
    for (int row0 = blockIdx.y * 32; row0 < nf; row0 += gridDim.y * 32) {
        float acc[2][4] = {{0.f,0.f,0.f,0.f},{0.f,0.f,0.f,0.f}};

        for (int k0 = 0; k0 < K; k0 += 32) {
            {
                int r  = tid >> 3;
                int kc = (tid & 7) << 2;
                int rr = row0 + r;
                if (rr >= nf) rr = nf - 1;
                int arow = rowmap ? rowmap[rr] : rr;
                float4 v = *reinterpret_cast<const float4*>(A + (size_t)arow * K + k0 + kc);
                As[r][kc] = v.x; As[r][kc + 1] = v.y; As[r][kc + 2] = v.z; As[r][kc + 3] = v.w;
            }
            {
#pragma unroll
                for (int it = 0; it < 2; it++) {
                    int f4 = tid + 256 * it;
                    int r  = f4 >> 4;
                    int cc = (f4 & 15) << 2;
                    float4 v = *reinterpret_cast<const float4*>(B + (size_t)(k0 + r) * N + col0 + cc);
                    *reinterpret_cast<float4*>(&Bs[r][cc]) = v;
                }
            }
            __syncthreads();
#pragma unroll
            for (int kk = 0; kk < 32; kk++) {
                float a0 = As[ty * 2][kk], a1 = As[ty * 2 + 1][kk];
                float b0 = Bs[kk][tx * 4], b1 = Bs[kk][tx * 4 + 1];
                float b2 = Bs[kk][tx * 4 + 2], b3 = Bs[kk][tx * 4 + 3];
                acc[0][0] = fmaf(a0, b0, acc[0][0]); acc[0][1] = fmaf(a0, b1, acc[0][1]);
                acc[0][2] = fmaf(a0, b2, acc[0][2]); acc[0][3] = fmaf(a0, b3, acc[0][3]);
                acc[1][0] = fmaf(a1, b0, acc[1][0]); acc[1][1] = fmaf(a1, b1, acc[1][1]);
                acc[1][2] = fmaf(a1, b2, acc[1][2]); acc[1][3] = fmaf(a1, b3, acc[1][3]);
            }
            __syncthreads();
        }
#pragma unroll
        for (int h = 0; h < 2; h++) {
            int r = row0 + ty * 2 + h;
            int c = col0 + tx * 4;
            float4 v;
            v.x = acc[h][0] + bias[c];     v.y = acc[h][1] + bias[c + 1];
            v.z = acc[h][2] + bias[c + 2]; v.w = acc[h][3] + bias[c + 3];
            if (RELU) {
                v.x = fmaxf(v.x, 0.f); v.y = fmaxf(v.y, 0.f);
                v.z = fmaxf(v.z, 0.f); v.w = fmaxf(v.w, 0.f);
            }
            *reinterpret_cast<float4*>(C + (size_t)r * N + c) = v;
        }
    }
}

// out[row,:] = dec3[idx[row],:]
__global__ void gather_out(float* __restrict__ out) {
    size_t total = (size_t)N_ROWS * (D_IN / 4);
    for (size_t i = (size_t)blockIdx.x * blockDim.x + threadIdx.x; i < total;
         i += (size_t)gridDim.x * blockDim.x) {
        int row = (int)(i / (D_IN / 4));
        int c4  = (int)(i % (D_IN / 4));
        int bi  = g_idx[row];
        float4 v = *reinterpret_cast<const float4*>(g_dec3 + (size_t)bi * D_IN + c4 * 4);
        *reinterpret_cast<float4*>(out + (size_t)row * D_IN + c4 * 4) = v;
    }
}

// ---------------- reduction helper ----------------
__device__ double block_reduce_sum(double v) {
    __shared__ double sh[32];
    int lane = threadIdx.x & 31, w = threadIdx.x >> 5;
#pragma unroll
    for (int o = 16; o > 0; o >>= 1) v += __shfl_down_sync(0xffffffffu, v, o);
    if (lane == 0) sh[w] = v;
    __syncthreads();
    int nw = (blockDim.x + 31) >> 5;
    v = (threadIdx.x < nw) ? sh[threadIdx.x] : 0.0;
    if (w == 0)
#pragma unroll
        for (int o = 16; o > 0; o >>= 1) v += __shfl_down_sync(0xffffffffu, v, o);
    return v;
}

// ---------------- small kernels ----------------
__global__ void init_kernel() {
    int t = threadIdx.x;
    if (t < 4) g_acc[t] = 0.0;
    if (t < N_CODE) g_cnt[t] = 0;
    if (t == 0) g_nflag = 0;
}

__global__ __launch_bounds__(128)
void vq_scan(const float* __restrict__ cb, const float* __restrict__ dots,
             float* __restrict__ out_idx, float* __restrict__ out_xq)
{
    __shared__ float scc[N_CODE];
    int tid = threadIdx.x;
    for (int c = tid; c < N_CODE; c += 128) {
        float s = 0.f;
#pragma unroll
        for (int e = 0; e < D_E; e++) { float w = cb[c * D_E + e]; s = fmaf(w, w, s); }
        scc[c] = s;
    }
    __syncthreads();

    float ccmax = 0.f;
    for (int c = 0; c < N_CODE; c++) ccmax = fmaxf(ccmax, scc[c]);

    int row = blockIdx.x * 128 + tid;
    float zr[D_E];
    float zz = 0.f;
#pragma unroll
    for (int e = 0; e < D_E; e++) {
        zr[e] = g_z[(size_t)row * D_E + e];
        zz = fmaf(zr[e], zr[e], zz);
    }
    const float4* drow = reinterpret_cast<const float4*>(dots + (size_t)row * N_CODE);
    float best = 3.4e38f, sec = 3.4e38f; int bi = 0;
    for (int c4 = 0; c4 < N_CODE / 4; c4++) {
        float4 dv = drow[c4];
        float dd[4] = {dv.x, dv.y, dv.z, dv.w};
#pragma unroll
        for (int j = 0; j < 4; j++) {
            int c = c4 * 4 + j;
            float d = zz - 2.f * dd[j] + scc[c];
            if (d < best) { sec = best; best = d; bi = c; }
            else if (d < sec) sec = d;
        }
    }

    float nz = sqrtf(zz), cmax = sqrtf(ccmax);
    float thresh = FLAG_EPS * nz * (nz + cmax) + 1e-7f;
    bool flagged = (sec - best) < thresh;

    float vq = 0.f;
    if (flagged) {
        int pos = atomicAdd(&g_nflag, 1);
        g_rowlist[pos] = row;
    } else {
        g_idx[row]   = bi;
        out_idx[row] = (float)bi;
#pragma unroll
        for (int e = 0; e < D_E; e++) {
            float xq = __ldg(cb + bi * D_E + e);
            out_xq[(size_t)row * D_E + e] = xq;
            float df = xq - zr[e];
            vq = fmaf(df, df, vq);
        }
        atomicAdd(&g_cnt[bi], 1);
    }
    double t = block_reduce_sum((double)vq);
    if (tid == 0) atomicAdd(&g_acc[0], t);
}

__global__ __launch_bounds__(256)
void repair_kernel(const float* __restrict__ cb, float* __restrict__ out_idx,
                   float* __restrict__ out_xq)
{
    __shared__ float zrow[D_E];
    __shared__ float dsh[N_CODE];
    __shared__ int   rwin;
    int tid = threadIdx.x;
    int nf = g_nflag;
    for (int i = blockIdx.x; i < nf; i += gridDim.x) {
        int row = g_rowlist[i];
        if (tid < D_E) zrow[tid] = g_zg[(size_t)i * D_E + tid];
        __syncthreads();
        float zz = 0.f;
#pragma unroll
        for (int e = 0; e < D_E; e++) zz = fmaf(zrow[e], zrow[e], zz);
        {
            int c = tid;
            float dot = 0.f, cc = 0.f;
#pragma unroll
            for (int e = 0; e < D_E; e++) {
                float w = __ldg(cb + c * D_E + e);
                dot = fmaf(zrow[e], w, dot);
                cc  = fmaf(w, w, cc);
            }
            dsh[c] = zz - 2.f * dot + cc;
        }
        __syncthreads();
        if (tid == 0) {
            float best = dsh[0]; int bi = 0;
            for (int c = 1; c < N_CODE; c++)
                if (dsh[c] < best) { best = dsh[c]; bi = c; }
            rwin = bi;
            g_idx[row] = bi;
            out_idx[row] = (float)bi;
            atomicAdd(&g_cnt[bi], 1);
        }
        __syncthreads();
        int bi = rwin;
        if (tid < D_E) {
            int e = tid;
            out_xq[(size_t)row * D_E + e] = __ldg(cb + bi * D_E + e);
            g_z[(size_t)row * D_E + e] = zrow[e];
        }
        if (tid == 0) {
            float vq = 0.f;
#pragma unroll
            for (int e = 0; e < D_E; e++) {
                float df = __ldg(cb + bi * D_E + e) - zrow[e];
                vq = fmaf(df, df, vq);
            }
            atomicAdd(&g_acc[0], (double)vq);
        }
        __syncthreads();
    }
}

// fused cos + trip + pair (block-range partition)
__global__ __launch_bounds__(256)
void losses_kernel(const float* __restrict__ qdw, const int* __restrict__ tr,
                   const int* __restrict__ pr)
{
    int b = blockIdx.x;
    double v = 0.0;
    int slot;
    if (b < 128) {
        slot = 1;
        int row = b * 256 + threadIdx.x;
        float dzq = 0.f, nz = 0.f, nq = 0.f;
#pragma unroll
        for (int e = 0; e < D_E; e++) {
            float zv = g_z [(size_t)row * D_E + e];
            float qv = g_qz[(size_t)row * D_E + e];
            dzq = fmaf(zv, qv, dzq);
            nz  = fmaf(zv, zv, nz);
            nq  = fmaf(qv, qv, nq);
        }
        float cosv = dzq / fmaxf(sqrtf(nz) * sqrtf(nq), 1e-8f);
        v = (double)(qdw[row] * cosv);
    } else if (b < 160) {
        slot = 2;
        int t = (b - 128) * 256 + threadIdx.x;
        if (t < N_TRIP) {
            int a = tr[3 * t], p = tr[3 * t + 1], n = tr[3 * t + 2];
            float sp = 0.f, sn = 0.f;
#pragma unroll
            for (int e = 0; e < D_E; e++) {
                float av = g_z[(size_t)a * D_E + e];
                float d1 = av - g_z[(size_t)p * D_E + e]; sp = fmaf(d1, d1, sp);
                float d2 = av - g_z[(size_t)n * D_E + e]; sn = fmaf(d2, d2, sn);
            }
            v = (double)fmaxf(sqrtf(sp + 1e-12f) - sqrtf(sn + 1e-12f) + 0.2f, 0.f);
        }
    } else {
        slot = 3;
        int k = (b - 160) * 256 + threadIdx.x;
        if (k < N_PAIR) {
            int ca = g_idx[pr[2 * k]];
            int cb2 = g_idx[pr[2 * k + 1]];
            v = (double)(g_lse[ca] - g_G[ca * N_CODE + cb2]);
        }
    }
    double s = block_reduce_sum(v);
    if (threadIdx.x == 0) atomicAdd(&g_acc[slot], s);
}

__global__ __launch_bounds__(256)
void code_stats(const float* __restrict__ cb) {
    int c = threadIdx.x;
    float myrow[D_E];
    float nrm = 0.f;
#pragma unroll
    for (int e = 0; e < D_E; e++) {
        myrow[e] = cb[c * D_E + e];
        nrm = fmaf(myrow[e], myrow[e], nrm);
    }
    nrm = fmaxf(sqrtf(nrm), 1e-12f);
#pragma unroll
    for (int e = 0; e < D_E; e++) { myrow[e] /= nrm; g_cbn[c * D_E + e] = myrow[e]; }
    __syncthreads();

    float m = -3.4e38f;
    for (int c2 = 0; c2 < N_CODE; c2++) {
        float dot = 0.f;
#pragma unroll
        for (int e = 0; e < D_E; e++) dot = fmaf(myrow[e], g_cbn[c2 * D_E + e], dot);
        float g = dot * 10.f;
        g_G[c * N_CODE + c2] = g;
        if (g_cnt[c2] > 0 && g > m) m = g;
    }
    double s = 0.0;
    for (int c2 = 0; c2 < N_CODE; c2++) {
        int cnt = g_cnt[c2];
        if (cnt > 0) s += (double)cnt * (double)expf(g_G[c * N_CODE + c2] - m);
    }
    g_lse[c] = m + (float)log(s);
}

__global__ void finalize_kernel(float* __restrict__ out) {
    out[VQ_OFF]    = (float)(g_acc[0] * 1.001 / ((double)N_ROWS * D_E));
    out[OUTER_OFF] = (float)(g_acc[3] / (double)N_PAIR);
    out[TRIP_OFF]  = (float)(g_acc[2] / (double)N_TRIP);
    out[QD_OFF]    = (float)(1.0 - g_acc[1] / (double)N_ROWS);
}

// ---------------- launch ----------------
extern "C" void kernel_launch(void* const* d_in, const int* in_sizes, int n_in,
                              void* d_out, int out_size)
{
    const float* x    = (const float*)d_in[0];
    const float* qe   = (const float*)d_in[1];
    const float* qdw  = (const float*)d_in[2];
    const int*   prs  = (const int*)  d_in[3];
    const int*   trs  = (const int*)  d_in[4];
    const float* ew0  = (const float*)d_in[5];
    const float* eb0  = (const float*)d_in[6];
    const float* ew1  = (const float*)d_in[7];
    const float* eb1  = (const float*)d_in[8];
    const float* ew2  = (const float*)d_in[9];
    const float* eb2  = (const float*)d_in[10];
    const float* dw0  = (const float*)d_in[11];
    const float* db0  = (const float*)d_in[12];
    const float* dw1  = (const float*)d_in[13];
    const float* db1  = (const float*)d_in[14];
    const float* dw2  = (const float*)d_in[15];
    const float* db2  = (const float*)d_in[16];
    const float* cb   = (const float*)d_in[17];
    float* out = (float*)d_out;

    cudaFuncSetAttribute(gemm_mma<64, true,  1, 3, false>, cudaFuncAttributeMaxDynamicSharedMemorySize, SMEM_STD);
    cudaFuncSetAttribute(gemm_mma<64, false, 0, 3, false>, cudaFuncAttributeMaxDynamicSharedMemorySize, SMEM_STD);
    cudaFuncSetAttribute(gemm_mma<64, false, 3, 3, false>, cudaFuncAttributeMaxDynamicSharedMemorySize, SMEM_STD);
    cudaFuncSetAttribute(gemm_mma<64, true,  2, 1, false>, cudaFuncAttributeMaxDynamicSharedMemorySize, SMEM_STD);
    cudaFuncSetAttribute(gemm_mma<64, false, 0, 1, false>, cudaFuncAttributeMaxDynamicSharedMemorySize, SMEM_STD);
    cudaFuncSetAttribute(gemm_mma<64, true,  1, 3, true >, cudaFuncAttributeMaxDynamicSharedMemorySize, SMEM_AF32_T3);
    cudaFuncSetAttribute(gemm_mma<64, true,  2, 1, true >, cudaFuncAttributeMaxDynamicSharedMemorySize, SMEM_AF32_T1);

    __half *wh, *wl, *a0h, *a0l, *a1h, *a1l, *cbh, *cbl, *dh1, *dl1, *dh2, *dl2;
    float *z, *qz, *zg, *rep1, *rep2, *dec3, *zero;
    int *rowlist, *nflag;
    cudaGetSymbolAddress((void**)&wh,  g_wh);
    cudaGetSymbolAddress((void**)&wl,  g_wl);
    cudaGetSymbolAddress((void**)&a0h, g_a0h);
    cudaGetSymbolAddress((void**)&a0l, g_a0l);
    cudaGetSymbolAddress((void**)&a1h, g_a1h);
    cudaGetSymbolAddress((void**)&a1l, g_a1l);
    cudaGetSymbolAddress((void**)&cbh, g_cbh);
    cudaGetSymbolAddress((void**)&cbl, g_cbl);
    cudaGetSymbolAddress((void**)&dh1, g_dh1);
    cudaGetSymbolAddress((void**)&dl1, g_dl1);
    cudaGetSymbolAddress((void**)&dh2, g_dh2);
    cudaGetSymbolAddress((void**)&dl2, g_dl2);
    cudaGetSymbolAddress((void**)&z,   g_z);
    cudaGetSymbolAddress((void**)&qz,  g_qz);
    cudaGetSymbolAddress((void**)&zg,  g_zg);
    cudaGetSymbolAddress((void**)&rep1, g_rep1);
    cudaGetSymbolAddress((void**)&rep2, g_rep2);
    cudaGetSymbolAddress((void**)&dec3, g_dec3);
    cudaGetSymbolAddress((void**)&zero, g_zero);
    cudaGetSymbolAddress((void**)&rowlist, g_rowlist);
    cudaGetSymbolAddress((void**)&nflag,   g_nflag);

    init_kernel<<<1, 256>>>();

    // weight transpose + split: all 6 in one launch
    {
        W6 d;
        const float* Ws[6]  = {ew0, ew1, ew2, dw0, dw1, dw2};
        const int   Ks[6]   = {D_IN, D_H1, D_H2, D_E, D_H2, D_H1};
        const int   Ns[6]   = {D_H1, D_H2, D_E, D_H2, D_H1, D_IN};
        const int   offs[6] = {W0_OFF, W1_OFF, W2_OFF, W3_OFF, W4_OFF, W5_OFF};
        int base = 0;
        for (int i = 0; i < 6; i++) {
            d.W[i]   = Ws[i];
            d.hi[i]  = wh + offs[i];
            d.lo[i]  = wl + offs[i];
            d.K[i]   = Ks[i];
            d.N[i]   = Ns[i];
            d.nbx[i] = Ns[i] / 32;
            d.base[i] = base;
            base += (Ks[i] / 32) * (Ns[i] / 32);
        }
        wprep_all<<<base, 256>>>(d);
    }

    // ---- decoder on 256 codebook rows; L1/L2 split-K for occupancy ----
    split_kernel<<<32, 256>>>(cb, cbh, cbl, (size_t)N_CODE * D_E);
    gemm_mma<64, true, 1, 3, false><<<dim3(16, 2), 256, SMEM_STD>>>(
        nullptr, cbh, cbl, wh + W3_OFF, wl + W3_OFF, db0, nullptr, dh1, dl1, D_H2, D_E, D_E, 0);
    gemm_mma<64, false, 0, 3, false><<<dim3(32, 2, 4), 256, SMEM_STD>>>(
        nullptr, dh1, dl1, wh + W4_OFF, wl + W4_OFF, zero, rep2, nullptr, nullptr,
        D_H1, D_H2, 256, (size_t)N_CODE * D_H1);
    reduce_split<true, 1><<<512, 256>>>(rep2, 4, (size_t)N_CODE * D_H1, D_H1, db1,
                                        nullptr, dh2, dl2, (size_t)N_CODE * D_H1 / 4);
    gemm_mma<64, false, 0, 3, false><<<dim3(12, 2, 8), 256, SMEM_STD>>>(
        nullptr, dh2, dl2, wh + W5_OFF, wl + W5_OFF, zero, rep2, nullptr, nullptr,
        D_IN, D_H1, 256, (size_t)N_CODE * D_IN);
    reduce_split<false, 0><<<192, 256>>>(rep2, 8, (size_t)N_CODE * D_IN, D_IN, db2,
                                         dec3, nullptr, nullptr, (size_t)N_CODE * D_IN / 4);

    // ---- encoder(x): L0 fused-split (fp32 A), 3-term; L2 emits z hi/lo ----
    gemm_mma<64, true,  1, 3, true ><<<dim3(32, 256), 256, SMEM_AF32_T3>>>(
        x, nullptr, nullptr, wh + W0_OFF, wl + W0_OFF, eb0, nullptr, a1h, a1l, D_H1, D_IN, D_IN, 0);
    gemm_mma<64, true,  1, 3, false><<<dim3(16, 256), 256, SMEM_STD>>>(
        nullptr, a1h, a1l, wh + W1_OFF, wl + W1_OFF, eb1, nullptr, a0h, a0l, D_H2, D_H1, D_H1, 0);
    gemm_mma<64, false, 3, 3, false><<<dim3( 1, 256), 256, SMEM_STD>>>(
        nullptr, a0h, a0l, wh + W2_OFF, wl + W2_OFF, eb2, z, a1h, a1l, D_E, D_H2, D_H2, 0);

    // ---- VQ: dots = z @ cb^T via mma, scan, exact fp32 repair ----
    gemm_mma<64, false, 0, 3, false><<<dim3( 4, 256), 256, SMEM_STD>>>(
        nullptr, a1h, a1l, cbh, cbl, zero, rep1, nullptr, nullptr, N_CODE, D_E, D_E, 0);
    vq_scan<<<256, 128>>>(cb, rep1, out + IDX_OFF, out + XQ_OFF);
    sgemm32<true ><<<dim3(32, 48), 256>>>(x,    ew0, eb0, rep1, rowlist, nflag, D_H1, D_IN);
    sgemm32<true ><<<dim3(16, 48), 256>>>(rep1, ew1, eb1, rep2, nullptr, nflag, D_H2, D_H1);
    sgemm32<false><<<dim3( 1, 48), 256>>>(rep2, ew2, eb2, zg,   nullptr, nflag, D_E,  D_H2);
    repair_kernel<<<512, 256>>>(cb, out + IDX_OFF, out + XQ_OFF);

    // ---- encoder(q_embs), 1-term with fused split on L0 ----
    gemm_mma<64, true,  2, 1, true ><<<dim3(32, 256), 256, SMEM_AF32_T1>>>(
        qe, nullptr, nullptr, wh + W0_OFF, nullptr, eb0, nullptr, a0h, nullptr, D_H1, D_IN, D_IN, 0);
    gemm_mma<64, true,  2, 1, false><<<dim3(16, 256), 256, SMEM_STD>>>(
        nullptr, a0h, nullptr, wh + W1_OFF, nullptr, eb1, nullptr, a1h, nullptr, D_H2, D_H1, D_H1, 0);
    gemm_mma<64, false, 0, 1, false><<<dim3( 1, 256), 256, SMEM_STD>>>(
        nullptr, a1h, nullptr, wh + W2_OFF, nullptr, eb2, qz, nullptr, nullptr, D_E, D_H2, D_H2, 0);

    // ---- losses ----
    code_stats<<<1, 256>>>(cb);
    losses_kernel<<<176, 256>>>(qdw, trs, prs);

    // ---- out = dec3[idx] ----
    gather_out<<<2048, 256>>>(out);

    finalize_kernel<<<1, 1>>>(out);
}

// round 15
// speedup vs baseline: 1.0047x; 1.0047x over previous
#include <cuda_runtime.h>
#include <cuda_fp16.h>
#include <math.h>
#include <stdint.h>

#define N_ROWS 32768
#define D_IN   768
#define D_H1   2048
#define D_H2   1024
#define D_E    64
#define N_CODE 256
#define N_PAIR 4096
#define N_TRIP 8192

#define VQ_OFF    25165824
#define IDX_OFF   25165825
#define XQ_OFF    25198593
#define OUTER_OFF 27295745
#define TRIP_OFF  27295746
#define QD_OFF    27295747

#define FLAG_EPS 2e-5f

// ---------------- scratch (device globals) ----------------
#define W0_OFF 0
#define W1_OFF 1572864
#define W2_OFF 3670016
#define W3_OFF 3735552
#define W4_OFF 3801088
#define W5_OFF 5898240
#define W_TOT  7471104
__device__ __align__(16) __half g_wh[W_TOT];
__device__ __align__(16) __half g_wl[W_TOT];

#define ACT_ELEMS ((size_t)N_ROWS * 2048)
__device__ __align__(16) __half g_a0h[ACT_ELEMS];
__device__ __align__(16) __half g_a0l[ACT_ELEMS];
__device__ __align__(16) __half g_a1h[ACT_ELEMS];   // also: zh after enc L2
__device__ __align__(16) __half g_a1l[ACT_ELEMS];   // also: zl after enc L2

// decoder-on-codebook buffers (M=256)
__device__ __align__(16) __half g_cbh[N_CODE * D_E];
__device__ __align__(16) __half g_cbl[N_CODE * D_E];
__device__ __align__(16) __half g_dh1[N_CODE * D_H2];
__device__ __align__(16) __half g_dl1[N_CODE * D_H2];
__device__ __align__(16) __half g_dh2[N_CODE * D_H1];
__device__ __align__(16) __half g_dl2[N_CODE * D_H1];
__device__ float g_dec3[N_CODE * D_IN];

__device__ float g_z [(size_t)N_ROWS * D_E];
__device__ float g_qz[(size_t)N_ROWS * D_E];
__device__ float g_zg[(size_t)N_ROWS * D_E];
__device__ float g_rep1[(size_t)N_ROWS * D_H1];   // also dots[32768,256]
__device__ float g_rep2[(size_t)N_ROWS * D_H2];   // also split-K partials
__device__ float g_cbn[N_CODE * D_E];
__device__ float g_G  [N_CODE * N_CODE];
__device__ float g_lse[N_CODE];
__device__ float g_zero[2048];
__device__ int   g_idx[N_ROWS];
__device__ int   g_cnt[N_CODE];
__device__ int   g_rowlist[N_ROWS];
__device__ int   g_nflag;
__device__ double g_acc[4];

// ---------------- helpers ----------------
__device__ __forceinline__ uint32_t smem_u32(const void* p) {
    uint32_t a;
    asm("{ .reg .u64 t; cvta.to.shared.u64 t, %1; cvt.u32.u64 %0, t; }" : "=r"(a) : "l"(p));
    return a;
}
#define LDSM4(r, a) \
    asm volatile("ldmatrix.sync.aligned.m8n8.x4.shared.b16 {%0,%1,%2,%3}, [%4];" \
        : "=r"((r)[0]), "=r"((r)[1]), "=r"((r)[2]), "=r"((r)[3]) : "r"(a))
#define MMA16816(d, a, b) \
    asm volatile("mma.sync.aligned.m16n8k16.row.col.f32.f16.f16.f32 " \
        "{%0,%1,%2,%3}, {%4,%5,%6,%7}, {%8,%9}, {%0,%1,%2,%3};" \
        : "+f"((d)[0]), "+f"((d)[1]), "+f"((d)[2]), "+f"((d)[3]) \
        : "r"((a)[0]), "r"((a)[1]), "r"((a)[2]), "r"((a)[3]), "r"((b)[0]), "r"((b)[1]))
#define CP_ASYNC16(sa, ga) \
    asm volatile("cp.async.cg.shared.global [%0], [%1], 16;" :: "r"(sa), "l"(ga))
#define CP_COMMIT() asm volatile("cp.async.commit_group;" ::: "memory")

// ---------------- prep kernels ----------------
__global__ void split_kernel(const float* __restrict__ src,
                             __half* __restrict__ hi,
                             __half* __restrict__ lo, size_t n) {
    for (size_t i = (size_t)blockIdx.x * blockDim.x + threadIdx.x; i < n;
         i += (size_t)gridDim.x * blockDim.x) {
        float v = src[i];
        __half h = __float2half(v);
        hi[i] = h;
        if (lo) lo[i] = __float2half(v - __half2float(h));
    }
}

// all-6-weights transpose + split, one launch; block 0 also runs init
struct W6 {
    const float* W[6];
    __half* hi[6];
    __half* lo[6];
    int K[6], N[6], base[6], nbx[6];
};

__global__ __launch_bounds__(256)
void wprep_all(W6 d) {
    __shared__ float t[32][33];
    if (blockIdx.x == 0) {          // fused init (no consumer until vq stage)
        int tt = threadIdx.x;
        if (tt < 4) g_acc[tt] = 0.0;
        if (tt < N_CODE) g_cnt[tt] = 0;
        if (tt == 0) g_nflag = 0;
    }
    int b = blockIdx.x;
    int w = 0;
#pragma unroll
    for (int i = 1; i < 6; i++) if (b >= d.base[i]) w = i;
    int bx = b - d.base[w];
    int nbx = d.nbx[w];
    int K = d.K[w], N = d.N[w];
    int nb = (bx % nbx) * 32;
    int kb = (bx / nbx) * 32;
    const float* W = d.W[w];
    __half* hi = d.hi[w];
    __half* lo = d.lo[w];

    int tx = threadIdx.x & 31, ty = threadIdx.x >> 5;
#pragma unroll
    for (int j = 0; j < 32; j += 8)
        t[ty + j][tx] = W[(size_t)(kb + ty + j) * N + nb + tx];
    __syncthreads();
#pragma unroll
    for (int j = 0; j < 32; j += 8) {
        float v = t[tx][ty + j];
        size_t o = (size_t)(nb + ty + j) * K + kb + tx;
        __half h = __float2half(v);
        hi[o] = h;
        lo[o] = __float2half(v - __half2float(h));
    }
}

// ---------------- fp16 multi-term mma GEMM (BN=64, 2 CTAs/SM) ----------------
// TERMS=3: AhBh+AlBh+AhBl; TERMS=1: AhBh.
// OMODE 0: fp32 out; 1: fp16 hi/lo; 2: fp16 hi only; 3: fp32 + hi/lo.
// AF32: A fp32 in gmem, fused hi/lo split (B: 4-ring/3-deep; A: 3-ring, 1 sync/iter).
// Split-K (std path only): gridDim.z slices of Kslice each.
template<int BN, bool RELU, int OMODE, int TERMS, bool AF32>
__global__ __launch_bounds__(256, 2)
void gemm_mma(const float* __restrict__ Af,
              const __half* __restrict__ Ahi, const __half* __restrict__ Alo,
              const __half* __restrict__ Bhi, const __half* __restrict__ Blo,
              const float* __restrict__ bias,
              float* __restrict__ Of,
              __half* __restrict__ Ohi, __half* __restrict__ Olo,
              int Nn, int K, int Kslice, size_t pstride)
{
    constexpr int WARPS_N = 2;
    constexpr int WM = 32;
    constexpr int WN = BN / WARPS_N;   // 32
    constexpr int MT = 2;
    constexpr int NT = WN / 8;         // 4
    constexpr int PITCH = 80;
    constexpr int BROWS = (TERMS == 3) ? 2 * BN : BN;
    constexpr int AROWS = (TERMS == 3) ? 256 : 128;
    constexpr int BSTAGE = BROWS * PITCH;
    constexpr int ASTAGE = AROWS * PITCH;
    constexpr int STAGE = (256 + 2 * BN) * PITCH;   // std stage stride
    constexpr int LROWS = (TERMS == 3) ? (256 + 2 * BN) : (128 + BN);

    extern __shared__ __align__(16) char sm[];
    const int tid  = threadIdx.x;
    const int lane = tid & 31, wid = tid >> 5;
    const int wm = wid / WARPS_N, wn = wid % WARPS_N;
    const int row0 = blockIdx.y * 128;
    const int col0 = blockIdx.x * BN;
    const int kstart = blockIdx.z * Kslice;
    const uint32_t sb = smem_u32(sm);
    const uint32_t sbA_af = sb + 4 * BSTAGE;   // AF32: A region after FOUR B stages

    const uint32_t aoff = ((lane & 7) + ((lane >> 3) & 1) * 8) * PITCH + ((lane >> 4) << 4);
    const uint32_t boff = ((lane & 7) + ((lane >> 4) & 1) * 8) * PITCH + (((lane >> 3) & 1) << 4);

    const int nk = Kslice >> 5;

    float acc[MT][NT][4];
#pragma unroll
    for (int mi = 0; mi < MT; mi++)
#pragma unroll
        for (int ni = 0; ni < NT; ni++)
#pragma unroll
            for (int q = 0; q < 4; q++) acc[mi][ni][q] = 0.f;

    auto do_mma = [&](uint32_t sA, uint32_t sB) {
#pragma unroll
        for (int ks = 0; ks < 2; ks++) {
            uint32_t kofs = ks * 32;
            uint32_t ah[MT][4], al[MT][4], bh[NT][2], bl[NT][2];
#pragma unroll
            for (int mi = 0; mi < MT; mi++) {
                uint32_t base = sA + (uint32_t)(wm * WM + mi * 16) * PITCH + aoff + kofs;
                LDSM4(ah[mi], base);
                if (TERMS == 3) LDSM4(al[mi], base + 128 * PITCH);
            }
#pragma unroll
            for (int np = 0; np < NT / 2; np++) {
                uint32_t base = sB + (uint32_t)(wn * WN + np * 16) * PITCH + boff + kofs;
                uint32_t r[4];
                LDSM4(r, base);
                bh[2 * np][0] = r[0]; bh[2 * np][1] = r[1];
                bh[2 * np + 1][0] = r[2]; bh[2 * np + 1][1] = r[3];
                if (TERMS == 3) {
                    LDSM4(r, base + BN * PITCH);
                    bl[2 * np][0] = r[0]; bl[2 * np][1] = r[1];
                    bl[2 * np + 1][0] = r[2]; bl[2 * np + 1][1] = r[3];
                }
            }
#pragma unroll
            for (int mi = 0; mi < MT; mi++)
#pragma unroll
                for (int ni = 0; ni < NT; ni++) MMA16816(acc[mi][ni], ah[mi], bh[ni]);
            if (TERMS == 3) {
#pragma unroll
                for (int mi = 0; mi < MT; mi++)
#pragma unroll
                    for (int ni = 0; ni < NT; ni++) MMA16816(acc[mi][ni], al[mi], bh[ni]);
#pragma unroll
                for (int mi = 0; mi < MT; mi++)
#pragma unroll
                    for (int ni = 0; ni < NT; ni++) MMA16816(acc[mi][ni], ah[mi], bl[ni]);
            }
        }
    };

    if constexpr (!AF32) {
        auto load_stage = [&](int i) {
            uint32_t sbase = sb + (i % 3) * STAGE;
            int k0 = kstart + (i << 5);
#pragma unroll
            for (int c = tid; c < LROWS * 4; c += 256) {
                int r = c >> 2, ch = c & 3;
                const __half* g;
                int srow = r;
                if (TERMS == 1) {
                    if (r < 128) g = Ahi + (size_t)(row0 + r) * K;
                    else { g = Bhi + (size_t)(col0 + r - 128) * K; srow = r + 128; }
                } else {
                    if (r < 128)            g = Ahi + (size_t)(row0 + r) * K;
                    else if (r < 256)       g = Alo + (size_t)(row0 + r - 128) * K;
                    else if (r < 256 + BN)  g = Bhi + (size_t)(col0 + r - 256) * K;
                    else                    g = Blo + (size_t)(col0 + r - 256 - BN) * K;
                }
                CP_ASYNC16(sbase + srow * PITCH + ch * 16, g + k0 + ch * 8);
            }
            CP_COMMIT();
        };
        load_stage(0);
        if (1 < nk) load_stage(1);
        for (int i = 0; i < nk; i++) {
            if (i + 1 < nk) asm volatile("cp.async.wait_group 1;" ::: "memory");
            else            asm volatile("cp.async.wait_group 0;" ::: "memory");
            __syncthreads();
            if (i + 2 < nk) load_stage(i + 2);
            uint32_t sA = sb + (i % 3) * STAGE;
            do_mma(sA, sA + 256 * PITCH);
        }
    } else {
        // B: 4-stage ring, 3-deep prefetch. A: LDG fp32 + fused split, 3-ring.
        auto load_B = [&](int i) {
            uint32_t sbase = sb + (i & 3) * BSTAGE;
            int k0 = i << 5;
#pragma unroll
            for (int c = tid; c < BROWS * 4; c += 256) {
                int r = c >> 2, ch = c & 3;
                const __half* g;
                if (TERMS == 3 && r >= BN) g = Blo + (size_t)(col0 + r - BN) * K;
                else                       g = Bhi + (size_t)(col0 + r) * K;
                CP_ASYNC16(sbase + r * PITCH + ch * 16, g + k0 + ch * 8);
            }
            CP_COMMIT();
        };
        float4 Ar[4], An[4];
        auto ldgA = [&](int i, float4* R) {
            int k0 = i << 5;
#pragma unroll
            for (int it = 0; it < 4; it++) {
                int f4 = tid + 256 * it;
                int r = f4 >> 3, c4 = f4 & 7;
                R[it] = *reinterpret_cast<const float4*>(
                    Af + (size_t)(row0 + r) * K + k0 + c4 * 4);
            }
        };
        auto cvtsts = [&](int i, const float4* R) {
            uint32_t abase = sbA_af + (i % 3) * ASTAGE;
#pragma unroll
            for (int it = 0; it < 4; it++) {
                int f4 = tid + 256 * it;
                int r = f4 >> 3, c4 = f4 & 7;
                uint32_t off = abase + (uint32_t)r * PITCH + c4 * 8;
                __half2 h01 = __floats2half2_rn(R[it].x, R[it].y);
                __half2 h23 = __floats2half2_rn(R[it].z, R[it].w);
                asm volatile("st.shared.v2.b32 [%0], {%1,%2};"
                    :: "r"(off), "r"(*(const uint32_t*)&h01), "r"(*(const uint32_t*)&h23));
                if (TERMS == 3) {
                    __half2 l01 = __floats2half2_rn(R[it].x - __half2float(__low2half(h01)),
                                                    R[it].y - __half2float(__high2half(h01)));
                    __half2 l23 = __floats2half2_rn(R[it].z - __half2float(__low2half(h23)),
                                                    R[it].w - __half2float(__high2half(h23)));
                    asm volatile("st.shared.v2.b32 [%0], {%1,%2};"
                        :: "r"(off + 128 * PITCH),
                           "r"(*(const uint32_t*)&l01), "r"(*(const uint32_t*)&l23));
                }
            }
        };
        ldgA(0, Ar);
        load_B(0);
        if (1 < nk) load_B(1);
        if (2 < nk) load_B(2);
        for (int i = 0; i < nk; i++) {
            if (i + 1 < nk) ldgA(i + 1, An);
            cvtsts(i, Ar);   // writes A-buf i%3; conflicting reader was do_mma(i-3) < sync(i-2)
            int rem = nk - 1 - i;
            if (rem >= 2)      asm volatile("cp.async.wait_group 2;" ::: "memory");
            else if (rem == 1) asm volatile("cp.async.wait_group 1;" ::: "memory");
            else               asm volatile("cp.async.wait_group 0;" ::: "memory");
            __syncthreads();
            if (i + 3 < nk) load_B(i + 3);   // writes (i+3)&3 != i&3
            do_mma(sbA_af + (i % 3) * ASTAGE, sb + (i & 3) * BSTAGE);
#pragma unroll
            for (int it = 0; it < 4; it++) Ar[it] = An[it];
        }
    }

#pragma unroll
    for (int mi = 0; mi < MT; mi++) {
        int rbase = row0 + wm * WM + mi * 16 + (lane >> 2);
#pragma unroll
        for (int ni = 0; ni < NT; ni++) {
            int c = col0 + wn * WN + ni * 8 + (lane & 3) * 2;
            float b0 = __ldg(&bias[c]), b1 = __ldg(&bias[c + 1]);
#pragma unroll
            for (int h = 0; h < 2; h++) {
                float v0 = acc[mi][ni][2 * h]     + b0;
                float v1 = acc[mi][ni][2 * h + 1] + b1;
                if (RELU) { v0 = fmaxf(v0, 0.f); v1 = fmaxf(v1, 0.f); }
                size_t o = (size_t)(rbase + 8 * h) * Nn + c + blockIdx.z * pstride;
                if (OMODE == 0 || OMODE == 3)
                    *reinterpret_cast<float2*>(Of + o) = make_float2(v0, v1);
                if (OMODE == 1 || OMODE == 2 || OMODE == 3) {
                    __half2 hh;
                    hh.x = __float2half(v0);
                    hh.y = __float2half(v1);
                    *reinterpret_cast<__half2*>(Ohi + o) = hh;
                    if (OMODE == 1 || OMODE == 3) {
                        __half2 ll;
                        ll.x = __float2half(v0 - __half2float(hh.x));
                        ll.y = __float2half(v1 - __half2float(hh.y));
                        *reinterpret_cast<__half2*>(Olo + o) = ll;
                    }
                }
            }
        }
    }
}

#define SMEM_STD      (3 * (256 + 128) * 80)                   // 92160
#define SMEM_AF32_T3  (4 * 128 * 80 + 3 * 256 * 80)            // 102400
#define SMEM_AF32_T1  (4 * 64 * 80 + 3 * 128 * 80)             // 51200

// ---------------- split-K reduce: C = act(sum_z P[z] + bias) ----------------
template<bool RELU, int OMODE>
__global__ __launch_bounds__(256)
void reduce_split(const float* __restrict__ P, int S, size_t slice, int Nn,
                  const float* __restrict__ bias,
                  float* __restrict__ Of, __half* __restrict__ Ohi, __half* __restrict__ Olo,
                  size_t total4)
{
    for (size_t i = (size_t)blockIdx.x * blockDim.x + threadIdx.x; i < total4;
         i += (size_t)gridDim.x * blockDim.x) {
        size_t e0 = i * 4;
        float4 s = *reinterpret_cast<const float4*>(P + e0);
        for (int z = 1; z < S; z++) {
            float4 v = *reinterpret_cast<const float4*>(P + z * slice + e0);
            s.x += v.x; s.y += v.y; s.z += v.z; s.w += v.w;
        }
        int c = (int)(e0 % Nn);
        s.x += bias[c]; s.y += bias[c + 1]; s.z += bias[c + 2]; s.w += bias[c + 3];
        if (RELU) {
            s.x = fmaxf(s.x, 0.f); s.y = fmaxf(s.y, 0.f);
            s.z = fmaxf(s.z, 0.f); s.w = fmaxf(s.w, 0.f);
        }
        if (OMODE == 0) {
            *reinterpret_cast<float4*>(Of + e0) = s;
        } else {
            __half2 h01 = __floats2half2_rn(s.x, s.y);
            __half2 h23 = __floats2half2_rn(s.z, s.w);
            __half2 l01 = __floats2half2_rn(s.x - __half2float(__low2half(h01)),
                                            s.y - __half2float(__high2half(h01)));
            __half2 l23 = __floats2half2_rn(s.z - __half2float(__low2half(h23)),
                                            s.w - __half2float(__high2half(h23)));
            *reinterpret_cast<__half2*>(Ohi + e0)     = h01;
            *reinterpret_cast<__half2*>(Ohi + e0 + 2) = h23;
            *reinterpret_cast<__half2*>(Olo + e0)     = l01;
            *reinterpret_cast<__half2*>(Olo + e0 + 2) = l23;
        }
    }
}

// ---------------- fp32 small-M GEMM (repair path; grid-strided rows) --------
template<bool RELU>
__global__ __launch_bounds__(256)
void sgemm32(const float* __restrict__ A, const float* __restrict__ B,
             const float* __restrict__ bias, float* __restrict__ C,
             const int* __restrict__ rowmap, const int* __restrict__ nf_ptr,
             int N, int K)
{
    const int nf = *nf_ptr;
    __shared__ float As[32][33];
    __shared__ float Bs[32][64];
    const int tid = threadIdx.x;
    const int ty = tid >> 4;
    const int tx = tid & 15;
    const int col0 = blockIdx.x * 64;

    for (int row0 = blockIdx.y * 32; row0 < nf; row0 += gridDim.y * 32) {
        float acc[2][4] = {{0.f,0.f,0.f,0.f},{0.f,0.f,0.f,0.f}};

        for (int k0 = 0; k0 < K; k0 += 32) {
            {
                int r  = tid >> 3;
                int kc = (tid & 7) << 2;
                int rr = row0 + r;
                if (rr >= nf) rr = nf - 1;
                int arow = rowmap ? rowmap[rr] : rr;
                float4 v = *reinterpret_cast<const float4*>(A + (size_t)arow * K + k0 + kc);
                As[r][kc] = v.x; As[r][kc + 1] = v.y; As[r][kc + 2] = v.z; As[r][kc + 3] = v.w;
            }
            {
#pragma unroll
                for (int it = 0; it < 2; it++) {
                    int f4 = tid + 256 * it;
                    int r  = f4 >> 4;
                    int cc = (f4 & 15) << 2;
                    float4 v = *reinterpret_cast<const float4*>(B + (size_t)(k0 + r) * N + col0 + cc);
                    *reinterpret_cast<float4*>(&Bs[r][cc]) = v;
                }
            }
            __syncthreads();
#pragma unroll
            for (int kk = 0; kk < 32; kk++) {
                float a0 = As[ty * 2][kk], a1 = As[ty * 2 + 1][kk];
                float b0 = Bs[kk][tx * 4], b1 = Bs[kk][tx * 4 + 1];
                float b2 = Bs[kk][tx * 4 + 2], b3 = Bs[kk][tx * 4 + 3];
                acc[0][0] = fmaf(a0, b0, acc[0][0]); acc[0][1] = fmaf(a0, b1, acc[0][1]);
                acc[0][2] = fmaf(a0, b2, acc[0][2]); acc[0][3] = fmaf(a0, b3, acc[0][3]);
                acc[1][0] = fmaf(a1, b0, acc[1][0]); acc[1][1] = fmaf(a1, b1, acc[1][1]);
                acc[1][2] = fmaf(a1, b2, acc[1][2]); acc[1][3] = fmaf(a1, b3, acc[1][3]);
            }
            __syncthreads();
        }
#pragma unroll
        for (int h = 0; h < 2; h++) {
            int r = row0 + ty * 2 + h;
            int c = col0 + tx * 4;
            float4 v;
            v.x = acc[h][0] + bias[c];     v.y = acc[h][1] + bias[c + 1];
            v.z = acc[h][2] + bias[c + 2]; v.w = acc[h][3] + bias[c + 3];
            if (RELU) {
                v.x = fmaxf(v.x, 0.f); v.y = fmaxf(v.y, 0.f);
                v.z = fmaxf(v.z, 0.f); v.w = fmaxf(v.w, 0.f);
            }
            *reinterpret_cast<float4*>(C + (size_t)r * N + c) = v;
        }
    }
}

// out[row,:] = dec3[idx[row],:]
__global__ void gather_out(float* __restrict__ out) {
    size_t total = (size_t)N_ROWS * (D_IN / 4);
    for (size_t i = (size_t)blockIdx.x * blockDim.x + threadIdx.x; i < total;
         i += (size_t)gridDim.x * blockDim.x) {
        int row = (int)(i / (D_IN / 4));
        int c4  = (int)(i % (D_IN / 4));
        int bi  = g_idx[row];
        float4 v = *reinterpret_cast<const float4*>(g_dec3 + (size_t)bi * D_IN + c4 * 4);
        *reinterpret_cast<float4*>(out + (size_t)row * D_IN + c4 * 4) = v;
    }
}

// ---------------- reduction helper ----------------
__device__ double block_reduce_sum(double v) {
    __shared__ double sh[32];
    int lane = threadIdx.x & 31, w = threadIdx.x >> 5;
#pragma unroll
    for (int o = 16; o > 0; o >>= 1) v += __shfl_down_sync(0xffffffffu, v, o);
    if (lane == 0) sh[w] = v;
    __syncthreads();
    int nw = (blockDim.x + 31) >> 5;
    v = (threadIdx.x < nw) ? sh[threadIdx.x] : 0.0;
    if (w == 0)
#pragma unroll
        for (int o = 16; o > 0; o >>= 1) v += __shfl_down_sync(0xffffffffu, v, o);
    return v;
}

// ---------------- small kernels ----------------
__global__ __launch_bounds__(128)
void vq_scan(const float* __restrict__ cb, const float* __restrict__ dots,
             float* __restrict__ out_idx, float* __restrict__ out_xq)
{
    __shared__ float scc[N_CODE];
    int tid = threadIdx.x;
    for (int c = tid; c < N_CODE; c += 128) {
        float s = 0.f;
#pragma unroll
        for (int e = 0; e < D_E; e++) { float w = cb[c * D_E + e]; s = fmaf(w, w, s); }
        scc[c] = s;
    }
    __syncthreads();

    float ccmax = 0.f;
    for (int c = 0; c < N_CODE; c++) ccmax = fmaxf(ccmax, scc[c]);

    int row = blockIdx.x * 128 + tid;
    float zr[D_E];
    float zz = 0.f;
#pragma unroll
    for (int e = 0; e < D_E; e++) {
        zr[e] = g_z[(size_t)row * D_E + e];
        zz = fmaf(zr[e], zr[e], zz);
    }
    const float4* drow = reinterpret_cast<const float4*>(dots + (size_t)row * N_CODE);
    float best = 3.4e38f, sec = 3.4e38f; int bi = 0;
    for (int c4 = 0; c4 < N_CODE / 4; c4++) {
        float4 dv = drow[c4];
        float dd[4] = {dv.x, dv.y, dv.z, dv.w};
#pragma unroll
        for (int j = 0; j < 4; j++) {
            int c = c4 * 4 + j;
            float d = zz - 2.f * dd[j] + scc[c];
            if (d < best) { sec = best; best = d; bi = c; }
            else if (d < sec) sec = d;
        }
    }

    float nz = sqrtf(zz), cmax = sqrtf(ccmax);
    float thresh = FLAG_EPS * nz * (nz + cmax) + 1e-7f;
    bool flagged = (sec - best) < thresh;

    float vq = 0.f;
    if (flagged) {
        int pos = atomicAdd(&g_nflag, 1);
        g_rowlist[pos] = row;
    } else {
        g_idx[row]   = bi;
        out_idx[row] = (float)bi;
#pragma unroll
        for (int e = 0; e < D_E; e++) {
            float xq = __ldg(cb + bi * D_E + e);
            out_xq[(size_t)row * D_E + e] = xq;
            float df = xq - zr[e];
            vq = fmaf(df, df, vq);
        }
        atomicAdd(&g_cnt[bi], 1);
    }
    double t = block_reduce_sum((double)vq);
    if (tid == 0) atomicAdd(&g_acc[0], t);
}

__global__ __launch_bounds__(256)
void repair_kernel(const float* __restrict__ cb, float* __restrict__ out_idx,
                   float* __restrict__ out_xq)
{
    __shared__ float zrow[D_E];
    __shared__ float dsh[N_CODE];
    __shared__ int   rwin;
    int tid = threadIdx.x;
    int nf = g_nflag;
    for (int i = blockIdx.x; i < nf; i += gridDim.x) {
        int row = g_rowlist[i];
        if (tid < D_E) zrow[tid] = g_zg[(size_t)i * D_E + tid];
        __syncthreads();
        float zz = 0.f;
#pragma unroll
        for (int e = 0; e < D_E; e++) zz = fmaf(zrow[e], zrow[e], zz);
        {
            int c = tid;
            float dot = 0.f, cc = 0.f;
#pragma unroll
            for (int e = 0; e < D_E; e++) {
                float w = __ldg(cb + c * D_E + e);
                dot = fmaf(zrow[e], w, dot);
                cc  = fmaf(w, w, cc);
            }
            dsh[c] = zz - 2.f * dot + cc;
        }
        __syncthreads();
        if (tid == 0) {
            float best = dsh[0]; int bi = 0;
            for (int c = 1; c < N_CODE; c++)
                if (dsh[c] < best) { best = dsh[c]; bi = c; }
            rwin = bi;
            g_idx[row] = bi;
            out_idx[row] = (float)bi;
            atomicAdd(&g_cnt[bi], 1);
        }
        __syncthreads();
        int bi = rwin;
        if (tid < D_E) {
            int e = tid;
            out_xq[(size_t)row * D_E + e] = __ldg(cb + bi * D_E + e);
            g_z[(size_t)row * D_E + e] = zrow[e];
        }
        if (tid == 0) {
            float vq = 0.f;
#pragma unroll
            for (int e = 0; e < D_E; e++) {
                float df = __ldg(cb + bi * D_E + e) - zrow[e];
                vq = fmaf(df, df, vq);
            }
            atomicAdd(&g_acc[0], (double)vq);
        }
        __syncthreads();
    }
}

// fused cos + trip + pair (block-range partition)
__global__ __launch_bounds__(256)
void losses_kernel(const float* __restrict__ qdw, const int* __restrict__ tr,
                   const int* __restrict__ pr)
{
    int b = blockIdx.x;
    double v = 0.0;
    int slot;
    if (b < 128) {
        slot = 1;
        int row = b * 256 + threadIdx.x;
        float dzq = 0.f, nz = 0.f, nq = 0.f;
#pragma unroll
        for (int e = 0; e < D_E; e++) {
            float zv = g_z [(size_t)row * D_E + e];
            float qv = g_qz[(size_t)row * D_E + e];
            dzq = fmaf(zv, qv, dzq);
            nz  = fmaf(zv, zv, nz);
            nq  = fmaf(qv, qv, nq);
        }
        float cosv = dzq / fmaxf(sqrtf(nz) * sqrtf(nq), 1e-8f);
        v = (double)(qdw[row] * cosv);
    } else if (b < 160) {
        slot = 2;
        int t = (b - 128) * 256 + threadIdx.x;
        if (t < N_TRIP) {
            int a = tr[3 * t], p = tr[3 * t + 1], n = tr[3 * t + 2];
            float sp = 0.f, sn = 0.f;
#pragma unroll
            for (int e = 0; e < D_E; e++) {
                float av = g_z[(size_t)a * D_E + e];
                float d1 = av - g_z[(size_t)p * D_E + e]; sp = fmaf(d1, d1, sp);
                float d2 = av - g_z[(size_t)n * D_E + e]; sn = fmaf(d2, d2, sn);
            }
            v = (double)fmaxf(sqrtf(sp + 1e-12f) - sqrtf(sn + 1e-12f) + 0.2f, 0.f);
        }
    } else {
        slot = 3;
        int k = (b - 160) * 256 + threadIdx.x;
        if (k < N_PAIR) {
            int ca = g_idx[pr[2 * k]];
            int cb2 = g_idx[pr[2 * k + 1]];
            v = (double)(g_lse[ca] - g_G[ca * N_CODE + cb2]);
        }
    }
    double s = block_reduce_sum(v);
    if (threadIdx.x == 0) atomicAdd(&g_acc[slot], s);
}

__global__ __launch_bounds__(256)
void code_stats(const float* __restrict__ cb) {
    int c = threadIdx.x;
    float myrow[D_E];
    float nrm = 0.f;
#pragma unroll
    for (int e = 0; e < D_E; e++) {
        myrow[e] = cb[c * D_E + e];
        nrm = fmaf(myrow[e], myrow[e], nrm);
    }
    nrm = fmaxf(sqrtf(nrm), 1e-12f);
#pragma unroll
    for (int e = 0; e < D_E; e++) { myrow[e] /= nrm; g_cbn[c * D_E + e] = myrow[e]; }
    __syncthreads();

    float m = -3.4e38f;
    for (int c2 = 0; c2 < N_CODE; c2++) {
        float dot = 0.f;
#pragma unroll
        for (int e = 0; e < D_E; e++) dot = fmaf(myrow[e], g_cbn[c2 * D_E + e], dot);
        float g = dot * 10.f;
        g_G[c * N_CODE + c2] = g;
        if (g_cnt[c2] > 0 && g > m) m = g;
    }
    double s = 0.0;
    for (int c2 = 0; c2 < N_CODE; c2++) {
        int cnt = g_cnt[c2];
        if (cnt > 0) s += (double)cnt * (double)expf(g_G[c * N_CODE + c2] - m);
    }
    g_lse[c] = m + (float)log(s);
}

__global__ void finalize_kernel(float* __restrict__ out) {
    out[VQ_OFF]    = (float)(g_acc[0] * 1.001 / ((double)N_ROWS * D_E));
    out[OUTER_OFF] = (float)(g_acc[3] / (double)N_PAIR);
    out[TRIP_OFF]  = (float)(g_acc[2] / (double)N_TRIP);
    out[QD_OFF]    = (float)(1.0 - g_acc[1] / (double)N_ROWS);
}

// ---------------- launch ----------------
extern "C" void kernel_launch(void* const* d_in, const int* in_sizes, int n_in,
                              void* d_out, int out_size)
{
    const float* x    = (const float*)d_in[0];
    const float* qe   = (const float*)d_in[1];
    const float* qdw  = (const float*)d_in[2];
    const int*   prs  = (const int*)  d_in[3];
    const int*   trs  = (const int*)  d_in[4];
    const float* ew0  = (const float*)d_in[5];
    const float* eb0  = (const float*)d_in[6];
    const float* ew1  = (const float*)d_in[7];
    const float* eb1  = (const float*)d_in[8];
    const float* ew2  = (const float*)d_in[9];
    const float* eb2  = (const float*)d_in[10];
    const float* dw0  = (const float*)d_in[11];
    const float* db0  = (const float*)d_in[12];
    const float* dw1  = (const float*)d_in[13];
    const float* db1  = (const float*)d_in[14];
    const float* dw2  = (const float*)d_in[15];
    const float* db2  = (const float*)d_in[16];
    const float* cb   = (const float*)d_in[17];
    float* out = (float*)d_out;

    cudaFuncSetAttribute(gemm_mma<64, true,  1, 3, false>, cudaFuncAttributeMaxDynamicSharedMemorySize, SMEM_STD);
    cudaFuncSetAttribute(gemm_mma<64, false, 0, 3, false>, cudaFuncAttributeMaxDynamicSharedMemorySize, SMEM_STD);
    cudaFuncSetAttribute(gemm_mma<64, false, 3, 3, false>, cudaFuncAttributeMaxDynamicSharedMemorySize, SMEM_STD);
    cudaFuncSetAttribute(gemm_mma<64, true,  2, 1, false>, cudaFuncAttributeMaxDynamicSharedMemorySize, SMEM_STD);
    cudaFuncSetAttribute(gemm_mma<64, false, 0, 1, false>, cudaFuncAttributeMaxDynamicSharedMemorySize, SMEM_STD);
    cudaFuncSetAttribute(gemm_mma<64, true,  1, 3, true >, cudaFuncAttributeMaxDynamicSharedMemorySize, SMEM_AF32_T3);
    cudaFuncSetAttribute(gemm_mma<64, true,  2, 1, true >, cudaFuncAttributeMaxDynamicSharedMemorySize, SMEM_AF32_T1);

    __half *wh, *wl, *a0h, *a0l, *a1h, *a1l, *cbh, *cbl, *dh1, *dl1, *dh2, *dl2;
    float *z, *qz, *zg, *rep1, *rep2, *dec3, *zero;
    int *rowlist, *nflag;
    cudaGetSymbolAddress((void**)&wh,  g_wh);
    cudaGetSymbolAddress((void**)&wl,  g_wl);
    cudaGetSymbolAddress((void**)&a0h, g_a0h);
    cudaGetSymbolAddress((void**)&a0l, g_a0l);
    cudaGetSymbolAddress((void**)&a1h, g_a1h);
    cudaGetSymbolAddress((void**)&a1l, g_a1l);
    cudaGetSymbolAddress((void**)&cbh, g_cbh);
    cudaGetSymbolAddress((void**)&cbl, g_cbl);
    cudaGetSymbolAddress((void**)&dh1, g_dh1);
    cudaGetSymbolAddress((void**)&dl1, g_dl1);
    cudaGetSymbolAddress((void**)&dh2, g_dh2);
    cudaGetSymbolAddress((void**)&dl2, g_dl2);
    cudaGetSymbolAddress((void**)&z,   g_z);
    cudaGetSymbolAddress((void**)&qz,  g_qz);
    cudaGetSymbolAddress((void**)&zg,  g_zg);
    cudaGetSymbolAddress((void**)&rep1, g_rep1);
    cudaGetSymbolAddress((void**)&rep2, g_rep2);
    cudaGetSymbolAddress((void**)&dec3, g_dec3);
    cudaGetSymbolAddress((void**)&zero, g_zero);
    cudaGetSymbolAddress((void**)&rowlist, g_rowlist);
    cudaGetSymbolAddress((void**)&nflag,   g_nflag);

    // weight transpose + split: all 6 in one launch (block 0 also runs init)
    {
        W6 d;
        const float* Ws[6]  = {ew0, ew1, ew2, dw0, dw1, dw2};
        const int   Ks[6]   = {D_IN, D_H1, D_H2, D_E, D_H2, D_H1};
        const int   Ns[6]   = {D_H1, D_H2, D_E, D_H2, D_H1, D_IN};
        const int   offs[6] = {W0_OFF, W1_OFF, W2_OFF, W3_OFF, W4_OFF, W5_OFF};
        int base = 0;
        for (int i = 0; i < 6; i++) {
            d.W[i]   = Ws[i];
            d.hi[i]  = wh + offs[i];
            d.lo[i]  = wl + offs[i];
            d.K[i]   = Ks[i];
            d.N[i]   = Ns[i];
            d.nbx[i] = Ns[i] / 32;
            d.base[i] = base;
            base += (Ks[i] / 32) * (Ns[i] / 32);
        }
        wprep_all<<<base, 256>>>(d);
    }

    // ---- decoder on 256 codebook rows; L1/L2 split-K for occupancy ----
    split_kernel<<<32, 256>>>(cb, cbh, cbl, (size_t)N_CODE * D_E);
    gemm_mma<64, true, 1, 3, false><<<dim3(16, 2), 256, SMEM_STD>>>(
        nullptr, cbh, cbl, wh + W3_OFF, wl + W3_OFF, db0, nullptr, dh1, dl1, D_H2, D_E, D_E, 0);
    gemm_mma<64, false, 0, 3, false><<<dim3(32, 2, 4), 256, SMEM_STD>>>(
        nullptr, dh1, dl1, wh + W4_OFF, wl + W4_OFF, zero, rep2, nullptr, nullptr,
        D_H1, D_H2, 256, (size_t)N_CODE * D_H1);
    reduce_split<true, 1><<<512, 256>>>(rep2, 4, (size_t)N_CODE * D_H1, D_H1, db1,
                                        nullptr, dh2, dl2, (size_t)N_CODE * D_H1 / 4);
    gemm_mma<64, false, 0, 3, false><<<dim3(12, 2, 8), 256, SMEM_STD>>>(
        nullptr, dh2, dl2, wh + W5_OFF, wl + W5_OFF, zero, rep2, nullptr, nullptr,
        D_IN, D_H1, 256, (size_t)N_CODE * D_IN);
    reduce_split<false, 0><<<192, 256>>>(rep2, 8, (size_t)N_CODE * D_IN, D_IN, db2,
                                         dec3, nullptr, nullptr, (size_t)N_CODE * D_IN / 4);

    // ---- encoder(x): L0 fused-split (fp32 A), 3-term; L2 emits z hi/lo ----
    gemm_mma<64, true,  1, 3, true ><<<dim3(32, 256), 256, SMEM_AF32_T3>>>(
        x, nullptr, nullptr, wh + W0_OFF, wl + W0_OFF, eb0, nullptr, a1h, a1l, D_H1, D_IN, D_IN, 0);
    gemm_mma<64, true,  1, 3, false><<<dim3(16, 256), 256, SMEM_STD>>>(
        nullptr, a1h, a1l, wh + W1_OFF, wl + W1_OFF, eb1, nullptr, a0h, a0l, D_H2, D_H1, D_H1, 0);
    gemm_mma<64, false, 3, 3, false><<<dim3( 1, 256), 256, SMEM_STD>>>(
        nullptr, a0h, a0l, wh + W2_OFF, wl + W2_OFF, eb2, z, a1h, a1l, D_E, D_H2, D_H2, 0);

    // ---- VQ: dots = z @ cb^T via mma, scan, exact fp32 repair ----
    gemm_mma<64, false, 0, 3, false><<<dim3( 4, 256), 256, SMEM_STD>>>(
        nullptr, a1h, a1l, cbh, cbl, zero, rep1, nullptr, nullptr, N_CODE, D_E, D_E, 0);
    vq_scan<<<256, 128>>>(cb, rep1, out + IDX_OFF, out + XQ_OFF);
    sgemm32<true ><<<dim3(32, 48), 256>>>(x,    ew0, eb0, rep1, rowlist, nflag, D_H1, D_IN);
    sgemm32<true ><<<dim3(16, 48), 256>>>(rep1, ew1, eb1, rep2, nullptr, nflag, D_H2, D_H1);
    sgemm32<false><<<dim3( 1, 48), 256>>>(rep2, ew2, eb2, zg,   nullptr, nflag, D_E,  D_H2);
    repair_kernel<<<512, 256>>>(cb, out + IDX_OFF, out + XQ_OFF);

    // ---- out = dec3[idx] (ready after repair; overlaps nothing but order is free) ----
    gather_out<<<2048, 256>>>(out);

    // ---- encoder(q_embs), 1-term with fused split on L0 ----
    gemm_mma<64, true,  2, 1, true ><<<dim3(32, 256), 256, SMEM_AF32_T1>>>(
        qe, nullptr, nullptr, wh + W0_OFF, nullptr, eb0, nullptr, a0h, nullptr, D_H1, D_IN, D_IN, 0);
    gemm_mma<64, true,  2, 1, false><<<dim3(16, 256), 256, SMEM_STD>>>(
        nullptr, a0h, nullptr, wh + W1_OFF, nullptr, eb1, nullptr, a1h, nullptr, D_H2, D_H1, D_H1, 0);
    gemm_mma<64, false, 0, 1, false><<<dim3( 1, 256), 256, SMEM_STD>>>(
        nullptr, a1h, nullptr, wh + W2_OFF, nullptr, eb2, qz, nullptr, nullptr, D_E, D_H2, D_H2, 0);

    // ---- losses ----
    code_stats<<<1, 256>>>(cb);
    losses_kernel<<<176, 256>>>(qdw, trs, prs);

    finalize_kernel<<<1, 1>>>(out);
}